// round 11
// baseline (speedup 1.0000x reference)
#include <cuda_runtime.h>
#include <cuda_bf16.h>
#include <cuda_fp16.h>
#include <stdint.h>

#define DI __device__ __forceinline__

namespace {
constexpr int Bn = 2, Cn = 128, Hn = 256, Wn = 256;
constexpr int NWIN = 128;   // B * 8 * 8 chess phases
constexpr int NT   = 1024;  // tokens per window (32x32)
constexpr int QKVN = 192;   // 32 q + 32 k + 128 v
constexpr float LOG2E = 1.4426950408889634f;
// proj tiles (R8 config)
constexpr int PROJ_MT = 64;
constexpr int PROJ_SMEM = PROJ_MT * Cn * 2 + Cn * QKVN * 2 + QKVN * 4;  // 66304
// attention: 4 rowg x 2 colg warps, M=32 N=64 per warp, 64-key k-tiles, 3 CTAs/SM
constexpr int QSTR = 40;                    // padded row stride Q/K (80B, conflict-free)
constexpr int KB   = 64;                    // keys per k-tile
constexpr int NKB  = NT / KB;               // 16
constexpr int SQ_ELEMS = 128 * QSTR;        // 5120
constexpr int SK_ELEMS = KB * QSTR;         // 2560 per buffer
constexpr int SV_ELEMS = KB * 128;          // 8192 per buffer
constexpr int ATTN_SMEM_BYTES = (SQ_ELEMS + 2 * SK_ELEMS + 2 * SV_ELEMS) * 2;  // 53248
}

// Scratch (static device globals; no runtime allocation)
__device__ __align__(16) __nv_bfloat16 g_XT [NWIN * NT * Cn];    // [win][tok][c]
__device__ __align__(16) __half        g_QKV[NWIN * NT * QKVN];  // f16 [win][tok][192]
__device__ __align__(16) __half        g_OW [NWIN * NT * Cn];    // f16 [win][tok][c]
__device__ __align__(16) __nv_bfloat16 g_W  [Cn * QKVN];         // packed weights [k][n]

// ---------------- helpers ----------------
DI uint32_t smem_u32(const void* p) { return (uint32_t)__cvta_generic_to_shared(p); }

DI void ldm_x4(uint32_t* d, uint32_t a) {
    asm volatile("ldmatrix.sync.aligned.m8n8.x4.shared.b16 {%0,%1,%2,%3}, [%4];"
                 : "=r"(d[0]), "=r"(d[1]), "=r"(d[2]), "=r"(d[3]) : "r"(a));
}
DI void ldm_x4t(uint32_t* d, uint32_t a) {
    asm volatile("ldmatrix.sync.aligned.m8n8.x4.trans.shared.b16 {%0,%1,%2,%3}, [%4];"
                 : "=r"(d[0]), "=r"(d[1]), "=r"(d[2]), "=r"(d[3]) : "r"(a));
}
DI void mma_bf16(float* c, const uint32_t* a, const uint32_t* b) {
    asm volatile("mma.sync.aligned.m16n8k16.row.col.f32.bf16.bf16.f32 "
                 "{%0,%1,%2,%3}, {%4,%5,%6,%7}, {%8,%9}, {%0,%1,%2,%3};"
                 : "+f"(c[0]), "+f"(c[1]), "+f"(c[2]), "+f"(c[3])
                 : "r"(a[0]), "r"(a[1]), "r"(a[2]), "r"(a[3]), "r"(b[0]), "r"(b[1]));
}
// f16 in / f16 accumulate
DI void mma_f16(uint32_t* c, const uint32_t* a, const uint32_t* b) {
    asm volatile("mma.sync.aligned.m16n8k16.row.col.f16.f16.f16.f16 "
                 "{%0,%1}, {%2,%3,%4,%5}, {%6,%7}, {%0,%1};"
                 : "+r"(c[0]), "+r"(c[1])
                 : "r"(a[0]), "r"(a[1]), "r"(a[2]), "r"(a[3]), "r"(b[0]), "r"(b[1]));
}
DI uint32_t pack_f16(float lo, float hi) {
    uint32_t d;
    asm("cvt.rn.f16x2.f32 %0, %1, %2;" : "=r"(d) : "f"(hi), "f"(lo));
    return d;
}
DI uint32_t ex2_f16x2(uint32_t a) {
    uint32_t d;
    asm("ex2.approx.f16x2 %0, %1;" : "=r"(d) : "r"(a));
    return d;
}
DI uint32_t hadd2(uint32_t a, uint32_t b) {
    uint32_t d;
    asm("add.f16x2 %0, %1, %2;" : "=r"(d) : "r"(a), "r"(b));
    return d;
}
DI float hsum(uint32_t a) {
    float lo, hi;
    asm("{\n\t.reg .b16 l, h;\n\tmov.b32 {l, h}, %2;\n\t"
        "cvt.f32.f16 %0, l;\n\tcvt.f32.f16 %1, h;\n\t}"
        : "=f"(lo), "=f"(hi) : "r"(a));
    return lo + hi;
}
DI void unpack_f16(uint32_t a, float& lo, float& hi) {
    asm("{\n\t.reg .b16 l, h;\n\tmov.b32 {l, h}, %2;\n\t"
        "cvt.f32.f16 %0, l;\n\tcvt.f32.f16 %1, h;\n\t}"
        : "=f"(lo), "=f"(hi) : "r"(a));
}
DI void cp16(uint32_t dst_smem, const void* src) {
    asm volatile("cp.async.cg.shared.global [%0], [%1], 16;" :: "r"(dst_smem), "l"(src));
}
DI void cp_commit() { asm volatile("cp.async.commit_group;"); }
DI void cp_wait0()  { asm volatile("cp.async.wait_group 0;"); }

// ---------------- kernel 0: pack weights (Wq pre-scaled by log2(e)) ----------------
__global__ void k_pack(const float* __restrict__ Wq, const float* __restrict__ Wk,
                       const float* __restrict__ Wv) {
    int idx = blockIdx.x * 256 + threadIdx.x;
    if (idx >= Cn * QKVN) return;
    int k = idx / QKVN, n = idx % QKVN;
    float v = (n < 32) ? Wq[n * Cn + k] * LOG2E
            : (n < 64) ? Wk[(n - 32) * Cn + k]
                       : Wv[(n - 64) * Cn + k];
    g_W[idx] = __float2bfloat16(v);
}

// ---------------- kernel 1: chess gather x -> XT ----------------
__global__ __launch_bounds__(256) void k_gather(const float* __restrict__ x) {
    __shared__ __align__(16) __nv_bfloat16 s[256 * 66];
    const int h = blockIdx.x, b = blockIdx.y, c0 = blockIdx.z * 64;
    const int tid = threadIdx.x;
    const float* xr = x + ((size_t)(b * Cn + c0) * Hn + h) * Wn;
#pragma unroll 8
    for (int c = 0; c < 64; c++)
        s[tid * 66 + c] = __float2bfloat16(xr[(size_t)c * Hn * Wn + tid]);
    __syncthreads();
    const int warp = tid >> 5, lane = tid & 31;
    const int i = h >> 3, py = h & 7;
#pragma unroll
    for (int it = 0; it < 32; it++) {
        int pair = it * 8 + warp;
        int px = pair >> 5, j = pair & 31;
        int wcol = j * 8 + px;
        uint32_t val = *(const uint32_t*)(s + wcol * 66 + 2 * lane);
        int win = b * 64 + py * 8 + px;
        int tok = i * 32 + j;
        *(uint32_t*)(g_XT + ((size_t)(win * NT + tok) * Cn + c0 + 2 * lane)) = val;
    }
}

// ---------------- kernel 2: QKV projection GEMM (R8 config) ----------------
__global__ __launch_bounds__(128, 3) void k_proj(const float* __restrict__ bq,
                                                 const float* __restrict__ bk,
                                                 const float* __restrict__ bv) {
    extern __shared__ __align__(16) char smem[];
    __nv_bfloat16* sX = (__nv_bfloat16*)smem;      // [64][128] swizzled
    __nv_bfloat16* sW = sX + PROJ_MT * Cn;         // [128][192] swizzled
    float* sBias = (float*)(sW + Cn * QKVN);       // [192]
    const int win = blockIdx.y, tb = blockIdx.x;
    const int tid = threadIdx.x, lane = tid & 31, warp = tid >> 5;
    for (int i = tid; i < 192; i += 128)
        sBias[i] = (i < 32) ? bq[i] * LOG2E : (i < 64) ? bk[i - 32] : bv[i - 64];

    const __nv_bfloat16* gX = g_XT + (size_t)(win * NT + tb * PROJ_MT) * Cn;
#pragma unroll
    for (int it = 0; it < 8; it++) {
        int idx = it * 128 + tid, r = idx >> 4, ch = idx & 15;
        int pch = (ch & 8) | ((ch ^ r) & 7);
        cp16(smem_u32(sX + r * 128 + pch * 8), gX + (size_t)r * Cn + ch * 8);
    }
#pragma unroll
    for (int it = 0; it < 24; it++) {
        int idx = it * 128 + tid, r = idx / 24, ch = idx % 24;
        int pch = (ch & 24) | ((ch ^ r) & 7);
        cp16(smem_u32(sW + r * QKVN + pch * 8), g_W + r * QKVN + ch * 8);
    }
    cp_commit();
    cp_wait0();
    __syncthreads();

    float acc[24][4];
#pragma unroll
    for (int t = 0; t < 24; t++)
#pragma unroll
        for (int q = 0; q < 4; q++) acc[t][q] = 0.f;

    const int m0 = warp * 16, mat = lane >> 3, rl = lane & 7;
    const uint32_t sXb = smem_u32(sX), sWb = smem_u32(sW);
#pragma unroll
    for (int kk = 0; kk < 8; kk++) {
        uint32_t a4[4];
        {
            int r = m0 + ((mat & 1) << 3) + rl;
            int ch = kk * 2 + (mat >> 1);
            int pch = (ch & 8) | ((ch ^ r) & 7);
            ldm_x4(a4, sXb + (uint32_t)(r * 256 + pch * 16));
        }
#pragma unroll
        for (int nt = 0; nt < 12; nt++) {
            uint32_t b4[4];
            int r = kk * 16 + ((mat & 1) << 3) + rl;
            int ch = nt * 2 + (mat >> 1);
            int pch = (ch & 24) | ((ch ^ r) & 7);
            ldm_x4t(b4, sWb + (uint32_t)(r * 384 + pch * 16));
            mma_bf16(acc[2 * nt], a4, b4);
            mma_bf16(acc[2 * nt + 1], a4, b4 + 2);
        }
    }
    const int row0 = m0 + (lane >> 2), tid4 = lane & 3;
    __half* gQ = g_QKV + (size_t)(win * NT + tb * PROJ_MT) * QKVN;
#pragma unroll
    for (int t = 0; t < 24; t++) {
        int col = t * 8 + tid4 * 2;
        float b0 = sBias[col], b1 = sBias[col + 1];
        *(uint32_t*)(gQ + (size_t)row0 * QKVN + col) =
            pack_f16(acc[t][0] + b0, acc[t][1] + b1);
        *(uint32_t*)(gQ + (size_t)(row0 + 8) * QKVN + col) =
            pack_f16(acc[t][2] + b0, acc[t][3] + b1);
    }
}

// ---------------- kernel 3: flash attention, f16 accum, col-split warps --------------
// grid (8 q-tiles of 128, 128 wins), 256 threads = 4 rowg x 2 colg warps.
// Each warp: M=32 q-rows x N=64 V-cols. 64-key k-tiles, 3 CTAs/SM.
__global__ __launch_bounds__(256, 3) void k_attn() {
    extern __shared__ __align__(16) char smem[];
    __half* sQ = (__half*)smem;                 // [128][QSTR]
    __half* sK = sQ + SQ_ELEMS;                 // 2 x [KB][QSTR]
    __half* sV = sK + 2 * SK_ELEMS;             // 2 x [KB][128] swizzled
    const int win = blockIdx.y, q0 = blockIdx.x * 128;
    const int tid = threadIdx.x, lane = tid & 31, warp = tid >> 5;
    const int rowg = warp >> 1, colg = warp & 1;
    const int mat = lane >> 3, rl = lane & 7, gid = lane >> 2, tid4 = lane & 3;
    const __half* gRow = g_QKV + (size_t)win * NT * QKVN;

    // prologue: Q tile (128 x 32) + K/V tile 0 (64 keys)
    {
#pragma unroll
        for (int it = 0; it < 2; it++) {
            int idx = it * 256 + tid, r = idx >> 2, ch = idx & 3;
            cp16(smem_u32(sQ + r * QSTR + ch * 8), gRow + (size_t)(q0 + r) * QKVN + ch * 8);
        }
        {
            int r = tid >> 2, ch = tid & 3;   // 64 rows x 4 chunks = 256
            cp16(smem_u32(sK + r * QSTR + ch * 8), gRow + (size_t)r * QKVN + 32 + ch * 8);
        }
#pragma unroll
        for (int it = 0; it < 4; it++) {      // 64 rows x 16 chunks = 1024
            int idx = it * 256 + tid, r = idx >> 4, ch = idx & 15;
            int pch = (ch & 8) | ((ch ^ r) & 7);
            cp16(smem_u32(sV + r * 128 + pch * 8), gRow + (size_t)r * QKVN + 64 + ch * 8);
        }
        cp_commit();
    }
    cp_wait0();
    __syncthreads();

    // Q fragments for both m16 halves of this warp's 32 rows
    uint32_t aQ[2][2][4];
    {
        uint32_t sQb = smem_u32(sQ);
#pragma unroll
        for (int mh = 0; mh < 2; mh++) {
            int r = rowg * 32 + mh * 16 + ((mat & 1) << 3) + rl;
            ldm_x4(aQ[mh][0], sQb + (uint32_t)(r * (QSTR * 2) + (mat >> 1) * 16));
            ldm_x4(aQ[mh][1], sQb + (uint32_t)(r * (QSTR * 2) + 32 + (mat >> 1) * 16));
        }
    }

    uint32_t O[2][8][2];   // f16x2 accumulators: [mh][col pair][reg] = 32 regs
#pragma unroll
    for (int mh = 0; mh < 2; mh++)
#pragma unroll
        for (int t = 0; t < 8; t++) { O[mh][t][0] = 0u; O[mh][t][1] = 0u; }
    float l[2][2] = {{0.f, 0.f}, {0.f, 0.f}};   // f32 rowsums [mh][row half]
    const uint32_t sKb = smem_u32(sK), sVb = smem_u32(sV);

    for (int kb = 0; kb < NKB; kb++) {
        const int buf = kb & 1;
        if (kb < NKB - 1) {
            const int nb = buf ^ 1;
            const __half* src = gRow + (size_t)((kb + 1) * KB) * QKVN;
            __half* dK = sK + nb * SK_ELEMS;
            __half* dV = sV + nb * SV_ELEMS;
            {
                int r = tid >> 2, ch = tid & 3;
                cp16(smem_u32(dK + r * QSTR + ch * 8), src + (size_t)r * QKVN + 32 + ch * 8);
            }
#pragma unroll
            for (int it = 0; it < 4; it++) {
                int idx = it * 256 + tid, r = idx >> 4, ch = idx & 15;
                int pch = (ch & 8) | ((ch ^ r) & 7);
                cp16(smem_u32(dV + r * 128 + pch * 8), src + (size_t)r * QKVN + 64 + ch * 8);
            }
            cp_commit();
        }

        const uint32_t kBase = sKb + buf * (SK_ELEMS * 2);
        const uint32_t vBase = sVb + buf * (SV_ELEMS * 2);
        uint32_t rs[2][2] = {{0u, 0u}, {0u, 0u}};   // f16x2 per-kb rowsums
#pragma unroll
        for (int g = 0; g < 4; g++) {
            // S = Q K^T for 32 rows x 16 keys (f16 accum)
            uint32_t S[2][2][2];
#pragma unroll
            for (int mh = 0; mh < 2; mh++)
#pragma unroll
                for (int n8 = 0; n8 < 2; n8++) { S[mh][n8][0] = 0u; S[mh][n8][1] = 0u; }
#pragma unroll
            for (int ks = 0; ks < 2; ks++) {
                uint32_t b4[4];
                int r = g * 16 + ((mat >> 1) << 3) + rl;
                int ch = ks * 2 + (mat & 1);
                ldm_x4(b4, kBase + (uint32_t)(r * (QSTR * 2) + ch * 16));
#pragma unroll
                for (int mh = 0; mh < 2; mh++) {
                    mma_f16(S[mh][0], aQ[mh][ks], b4);
                    mma_f16(S[mh][1], aQ[mh][ks], b4 + 2);
                }
            }
            // P = 2^S in place; P == A-fragment layout for PV
            uint32_t aP[2][4];
#pragma unroll
            for (int mh = 0; mh < 2; mh++) {
                aP[mh][0] = ex2_f16x2(S[mh][0][0]);
                aP[mh][1] = ex2_f16x2(S[mh][0][1]);
                aP[mh][2] = ex2_f16x2(S[mh][1][0]);
                aP[mh][3] = ex2_f16x2(S[mh][1][1]);
                rs[mh][0] = hadd2(rs[mh][0], hadd2(aP[mh][0], aP[mh][2]));
                rs[mh][1] = hadd2(rs[mh][1], hadd2(aP[mh][1], aP[mh][3]));
            }
            // O += P V for this warp's 64 V-cols
#pragma unroll
            for (int nt = 0; nt < 4; nt++) {
                uint32_t b4[4];
                int r = g * 16 + ((mat & 1) << 3) + rl;
                int ch = colg * 8 + nt * 2 + (mat >> 1);
                int pch = (ch & 8) | ((ch ^ r) & 7);
                ldm_x4t(b4, vBase + (uint32_t)(r * 256 + pch * 16));
#pragma unroll
                for (int mh = 0; mh < 2; mh++) {
                    mma_f16(O[mh][2 * nt], aP[mh], b4);
                    mma_f16(O[mh][2 * nt + 1], aP[mh], b4 + 2);
                }
            }
        }
        // flush per-kb f16 rowsums to f32
#pragma unroll
        for (int mh = 0; mh < 2; mh++) {
            l[mh][0] += hsum(rs[mh][0]);
            l[mh][1] += hsum(rs[mh][1]);
        }

        if (kb < NKB - 1) {
            cp_wait0();
            __syncthreads();
        }
    }

    __half* gO = g_OW + (size_t)win * NT * Cn;
#pragma unroll
    for (int mh = 0; mh < 2; mh++) {
        float l0 = l[mh][0], l1 = l[mh][1];
        l0 += __shfl_xor_sync(0xffffffffu, l0, 1);
        l0 += __shfl_xor_sync(0xffffffffu, l0, 2);
        l1 += __shfl_xor_sync(0xffffffffu, l1, 1);
        l1 += __shfl_xor_sync(0xffffffffu, l1, 2);
        float inv0 = 1.f / l0, inv1 = 1.f / l1;
        const int row = q0 + rowg * 32 + mh * 16 + gid;
#pragma unroll
        for (int t = 0; t < 8; t++) {
            int col = colg * 64 + t * 8 + tid4 * 2;
            float a, b;
            unpack_f16(O[mh][t][0], a, b);
            *(uint32_t*)(gO + (size_t)row * Cn + col) = pack_f16(a * inv0, b * inv0);
            unpack_f16(O[mh][t][1], a, b);
            *(uint32_t*)(gO + (size_t)(row + 8) * Cn + col) = pack_f16(a * inv1, b * inv1);
        }
    }
}

// ---------------- kernel 4: chess reverse + gamma*out + x ----------------
__global__ __launch_bounds__(256) void k_scatter(const float* __restrict__ x,
                                                 const float* __restrict__ gamma,
                                                 float* __restrict__ out) {
    __shared__ __align__(16) __half s[256 * 66];
    const int h = blockIdx.x, b = blockIdx.y, c0 = blockIdx.z * 64;
    const int tid = threadIdx.x, warp = tid >> 5, lane = tid & 31;
    const int i = h >> 3, py = h & 7;
#pragma unroll
    for (int it = 0; it < 32; it++) {
        int pair = it * 8 + warp;
        int px = pair >> 5, j = pair & 31;
        int win = b * 64 + py * 8 + px;
        int tok = i * 32 + j;
        uint32_t v = *(const uint32_t*)(g_OW + ((size_t)(win * NT + tok) * Cn + c0 + 2 * lane));
        *(uint32_t*)(s + (j * 8 + px) * 66 + 2 * lane) = v;
    }
    __syncthreads();
    const float gm = gamma[0];
    const float* xr = x + ((size_t)(b * Cn + c0) * Hn + h) * Wn;
    float* orow = out + ((size_t)(b * Cn + c0) * Hn + h) * Wn;
#pragma unroll 8
    for (int c = 0; c < 64; c++) {
        float o = __half2float(s[tid * 66 + c]);
        orow[(size_t)c * Hn * Wn + tid] = gm * o + xr[(size_t)c * Hn * Wn + tid];
    }
}

// ---------------- launch ----------------
extern "C" void kernel_launch(void* const* d_in, const int* in_sizes, int n_in,
                              void* d_out, int out_size) {
    const float* x  = (const float*)d_in[0];
    const float* Wq = (const float*)d_in[1];
    const float* bq = (const float*)d_in[2];
    const float* Wk = (const float*)d_in[3];
    const float* bk = (const float*)d_in[4];
    const float* Wv = (const float*)d_in[5];
    const float* bv = (const float*)d_in[6];
    const float* gamma = (const float*)d_in[7];

    cudaFuncSetAttribute(k_proj, cudaFuncAttributeMaxDynamicSharedMemorySize, PROJ_SMEM);
    cudaFuncSetAttribute(k_attn, cudaFuncAttributeMaxDynamicSharedMemorySize, ATTN_SMEM_BYTES);

    k_pack<<<(Cn * QKVN + 255) / 256, 256>>>(Wq, Wk, Wv);
    k_gather<<<dim3(Hn, Bn, 2), 256>>>(x);
    k_proj<<<dim3(NT / PROJ_MT, NWIN), 128, PROJ_SMEM>>>(bq, bk, bv);
    k_attn<<<dim3(8, NWIN), 256, ATTN_SMEM_BYTES>>>();
    k_scatter<<<dim3(Hn, Bn, 2), 256>>>(x, gamma, (float*)d_out);
}

// round 12
// speedup vs baseline: 1.1076x; 1.1076x over previous
#include <cuda_runtime.h>
#include <cuda_bf16.h>
#include <cuda_fp16.h>
#include <stdint.h>

#define DI __device__ __forceinline__

namespace {
constexpr int Bn = 2, Cn = 128, Hn = 256, Wn = 256;
constexpr int NWIN = 128;   // B * 8 * 8 chess phases
constexpr int NT   = 1024;  // tokens per window (32x32)
constexpr int QKVN = 192;   // 32 q + 32 k + 128 v
constexpr float LOG2E = 1.4426950408889634f;
// proj tiles (R8 config)
constexpr int PROJ_MT = 64;
constexpr int PROJ_SMEM = PROJ_MT * Cn * 2 + Cn * QKVN * 2 + QKVN * 4;  // 66304
// attention: M=16/warp, q-tile 128, 64-key k-tiles, TRIPLE buffered, 3 CTAs/SM
constexpr int QSTR = 40;                    // padded row stride Q/K (80B, conflict-free)
constexpr int KB   = 64;                    // keys per k-tile
constexpr int NKB  = NT / KB;               // 16
constexpr int SQ_ELEMS = 128 * QSTR;        // 5120
constexpr int SK_ELEMS = KB * QSTR;         // 2560 per buffer
constexpr int SV_ELEMS = KB * 128;          // 8192 per buffer
constexpr int ATTN_SMEM_BYTES = (SQ_ELEMS + 3 * SK_ELEMS + 3 * SV_ELEMS) * 2;  // 74752
}

// Scratch (static device globals; no runtime allocation)
__device__ __align__(16) __nv_bfloat16 g_XT [NWIN * NT * Cn];    // [win][tok][c]
__device__ __align__(16) __half        g_QKV[NWIN * NT * QKVN];  // f16 [win][tok][192]
__device__ __align__(16) __half        g_OW [NWIN * NT * Cn];    // f16 [win][tok][c]
__device__ __align__(16) __nv_bfloat16 g_W  [Cn * QKVN];         // packed weights [k][n]

// ---------------- helpers ----------------
DI uint32_t smem_u32(const void* p) { return (uint32_t)__cvta_generic_to_shared(p); }

DI void ldm_x4(uint32_t* d, uint32_t a) {
    asm volatile("ldmatrix.sync.aligned.m8n8.x4.shared.b16 {%0,%1,%2,%3}, [%4];"
                 : "=r"(d[0]), "=r"(d[1]), "=r"(d[2]), "=r"(d[3]) : "r"(a));
}
DI void ldm_x4t(uint32_t* d, uint32_t a) {
    asm volatile("ldmatrix.sync.aligned.m8n8.x4.trans.shared.b16 {%0,%1,%2,%3}, [%4];"
                 : "=r"(d[0]), "=r"(d[1]), "=r"(d[2]), "=r"(d[3]) : "r"(a));
}
DI void mma_bf16(float* c, const uint32_t* a, const uint32_t* b) {
    asm volatile("mma.sync.aligned.m16n8k16.row.col.f32.bf16.bf16.f32 "
                 "{%0,%1,%2,%3}, {%4,%5,%6,%7}, {%8,%9}, {%0,%1,%2,%3};"
                 : "+f"(c[0]), "+f"(c[1]), "+f"(c[2]), "+f"(c[3])
                 : "r"(a[0]), "r"(a[1]), "r"(a[2]), "r"(a[3]), "r"(b[0]), "r"(b[1]));
}
// f16 in / f16 accumulate
DI void mma_f16(uint32_t* c, const uint32_t* a, const uint32_t* b) {
    asm volatile("mma.sync.aligned.m16n8k16.row.col.f16.f16.f16.f16 "
                 "{%0,%1}, {%2,%3,%4,%5}, {%6,%7}, {%0,%1};"
                 : "+r"(c[0]), "+r"(c[1])
                 : "r"(a[0]), "r"(a[1]), "r"(a[2]), "r"(a[3]), "r"(b[0]), "r"(b[1]));
}
DI uint32_t pack_f16(float lo, float hi) {
    uint32_t d;
    asm("cvt.rn.f16x2.f32 %0, %1, %2;" : "=r"(d) : "f"(hi), "f"(lo));
    return d;
}
DI uint32_t ex2_f16x2(uint32_t a) {
    uint32_t d;
    asm("ex2.approx.f16x2 %0, %1;" : "=r"(d) : "r"(a));
    return d;
}
DI uint32_t hadd2(uint32_t a, uint32_t b) {
    uint32_t d;
    asm("add.f16x2 %0, %1, %2;" : "=r"(d) : "r"(a), "r"(b));
    return d;
}
DI float hsum(uint32_t a) {
    float lo, hi;
    asm("{\n\t.reg .b16 l, h;\n\tmov.b32 {l, h}, %2;\n\t"
        "cvt.f32.f16 %0, l;\n\tcvt.f32.f16 %1, h;\n\t}"
        : "=f"(lo), "=f"(hi) : "r"(a));
    return lo + hi;
}
DI void unpack_f16(uint32_t a, float& lo, float& hi) {
    asm("{\n\t.reg .b16 l, h;\n\tmov.b32 {l, h}, %2;\n\t"
        "cvt.f32.f16 %0, l;\n\tcvt.f32.f16 %1, h;\n\t}"
        : "=f"(lo), "=f"(hi) : "r"(a));
}
DI void cp16(uint32_t dst_smem, const void* src) {
    asm volatile("cp.async.cg.shared.global [%0], [%1], 16;" :: "r"(dst_smem), "l"(src));
}
DI void cp_commit() { asm volatile("cp.async.commit_group;"); }
DI void cp_wait0()  { asm volatile("cp.async.wait_group 0;"); }
DI void cp_wait1()  { asm volatile("cp.async.wait_group 1;"); }

// ---------------- kernel 0: pack weights (Wq pre-scaled by log2(e)) ----------------
__global__ void k_pack(const float* __restrict__ Wq, const float* __restrict__ Wk,
                       const float* __restrict__ Wv) {
    int idx = blockIdx.x * 256 + threadIdx.x;
    if (idx >= Cn * QKVN) return;
    int k = idx / QKVN, n = idx % QKVN;
    float v = (n < 32) ? Wq[n * Cn + k] * LOG2E
            : (n < 64) ? Wk[(n - 32) * Cn + k]
                       : Wv[(n - 64) * Cn + k];
    g_W[idx] = __float2bfloat16(v);
}

// ---------------- kernel 1: chess gather x -> XT ----------------
__global__ __launch_bounds__(256) void k_gather(const float* __restrict__ x) {
    __shared__ __align__(16) __nv_bfloat16 s[256 * 66];
    const int h = blockIdx.x, b = blockIdx.y, c0 = blockIdx.z * 64;
    const int tid = threadIdx.x;
    const float* xr = x + ((size_t)(b * Cn + c0) * Hn + h) * Wn;
#pragma unroll 8
    for (int c = 0; c < 64; c++)
        s[tid * 66 + c] = __float2bfloat16(xr[(size_t)c * Hn * Wn + tid]);
    __syncthreads();
    const int warp = tid >> 5, lane = tid & 31;
    const int i = h >> 3, py = h & 7;
#pragma unroll
    for (int it = 0; it < 32; it++) {
        int pair = it * 8 + warp;
        int px = pair >> 5, j = pair & 31;
        int wcol = j * 8 + px;
        uint32_t val = *(const uint32_t*)(s + wcol * 66 + 2 * lane);
        int win = b * 64 + py * 8 + px;
        int tok = i * 32 + j;
        *(uint32_t*)(g_XT + ((size_t)(win * NT + tok) * Cn + c0 + 2 * lane)) = val;
    }
}

// ---------------- kernel 2: QKV projection GEMM (R8 config) ----------------
__global__ __launch_bounds__(128, 3) void k_proj(const float* __restrict__ bq,
                                                 const float* __restrict__ bk,
                                                 const float* __restrict__ bv) {
    extern __shared__ __align__(16) char smem[];
    __nv_bfloat16* sX = (__nv_bfloat16*)smem;      // [64][128] swizzled
    __nv_bfloat16* sW = sX + PROJ_MT * Cn;         // [128][192] swizzled
    float* sBias = (float*)(sW + Cn * QKVN);       // [192]
    const int win = blockIdx.y, tb = blockIdx.x;
    const int tid = threadIdx.x, lane = tid & 31, warp = tid >> 5;
    for (int i = tid; i < 192; i += 128)
        sBias[i] = (i < 32) ? bq[i] * LOG2E : (i < 64) ? bk[i - 32] : bv[i - 64];

    const __nv_bfloat16* gX = g_XT + (size_t)(win * NT + tb * PROJ_MT) * Cn;
#pragma unroll
    for (int it = 0; it < 8; it++) {
        int idx = it * 128 + tid, r = idx >> 4, ch = idx & 15;
        int pch = (ch & 8) | ((ch ^ r) & 7);
        cp16(smem_u32(sX + r * 128 + pch * 8), gX + (size_t)r * Cn + ch * 8);
    }
#pragma unroll
    for (int it = 0; it < 24; it++) {
        int idx = it * 128 + tid, r = idx / 24, ch = idx % 24;
        int pch = (ch & 24) | ((ch ^ r) & 7);
        cp16(smem_u32(sW + r * QKVN + pch * 8), g_W + r * QKVN + ch * 8);
    }
    cp_commit();
    cp_wait0();
    __syncthreads();

    float acc[24][4];
#pragma unroll
    for (int t = 0; t < 24; t++)
#pragma unroll
        for (int q = 0; q < 4; q++) acc[t][q] = 0.f;

    const int m0 = warp * 16, mat = lane >> 3, rl = lane & 7;
    const uint32_t sXb = smem_u32(sX), sWb = smem_u32(sW);
#pragma unroll
    for (int kk = 0; kk < 8; kk++) {
        uint32_t a4[4];
        {
            int r = m0 + ((mat & 1) << 3) + rl;
            int ch = kk * 2 + (mat >> 1);
            int pch = (ch & 8) | ((ch ^ r) & 7);
            ldm_x4(a4, sXb + (uint32_t)(r * 256 + pch * 16));
        }
#pragma unroll
        for (int nt = 0; nt < 12; nt++) {
            uint32_t b4[4];
            int r = kk * 16 + ((mat & 1) << 3) + rl;
            int ch = nt * 2 + (mat >> 1);
            int pch = (ch & 24) | ((ch ^ r) & 7);
            ldm_x4t(b4, sWb + (uint32_t)(r * 384 + pch * 16));
            mma_bf16(acc[2 * nt], a4, b4);
            mma_bf16(acc[2 * nt + 1], a4, b4 + 2);
        }
    }
    const int row0 = m0 + (lane >> 2), tid4 = lane & 3;
    __half* gQ = g_QKV + (size_t)(win * NT + tb * PROJ_MT) * QKVN;
#pragma unroll
    for (int t = 0; t < 24; t++) {
        int col = t * 8 + tid4 * 2;
        float b0 = sBias[col], b1 = sBias[col + 1];
        *(uint32_t*)(gQ + (size_t)row0 * QKVN + col) =
            pack_f16(acc[t][0] + b0, acc[t][1] + b1);
        *(uint32_t*)(gQ + (size_t)(row0 + 8) * QKVN + col) =
            pack_f16(acc[t][2] + b0, acc[t][3] + b1);
    }
}

// ---------------- kernel 3: flash attention, f16 accum, M=16/warp, triple buffer ----
// grid (8 q-tiles of 128, 128 wins), 256 threads = 8 warps, 3 CTAs/SM (73KB smem).
__global__ __launch_bounds__(256, 3) void k_attn() {
    extern __shared__ __align__(16) char smem[];
    __half* sQ = (__half*)smem;                 // [128][QSTR]
    __half* sK = sQ + SQ_ELEMS;                 // 3 x [KB][QSTR]
    __half* sV = sK + 3 * SK_ELEMS;             // 3 x [KB][128] swizzled
    const int win = blockIdx.y, q0 = blockIdx.x * 128;
    const int tid = threadIdx.x, lane = tid & 31, warp = tid >> 5;
    const int mat = lane >> 3, rl = lane & 7, gid = lane >> 2, tid4 = lane & 3;
    const __half* gRow = g_QKV + (size_t)win * NT * QKVN;

    // prologue: Q + K/V tile 0 (group 1), K/V tile 1 (group 2)
    {
#pragma unroll
        for (int it = 0; it < 2; it++) {
            int idx = it * 256 + tid, r = idx >> 2, ch = idx & 3;
            cp16(smem_u32(sQ + r * QSTR + ch * 8), gRow + (size_t)(q0 + r) * QKVN + ch * 8);
        }
        {
            int r = tid >> 2, ch = tid & 3;
            cp16(smem_u32(sK + r * QSTR + ch * 8), gRow + (size_t)r * QKVN + 32 + ch * 8);
        }
#pragma unroll
        for (int it = 0; it < 4; it++) {
            int idx = it * 256 + tid, r = idx >> 4, ch = idx & 15;
            int pch = (ch & 8) | ((ch ^ r) & 7);
            cp16(smem_u32(sV + r * 128 + pch * 8), gRow + (size_t)r * QKVN + 64 + ch * 8);
        }
        cp_commit();
        // tile 1 into buffer 1
        const __half* src = gRow + (size_t)KB * QKVN;
        {
            int r = tid >> 2, ch = tid & 3;
            cp16(smem_u32(sK + SK_ELEMS + r * QSTR + ch * 8), src + (size_t)r * QKVN + 32 + ch * 8);
        }
#pragma unroll
        for (int it = 0; it < 4; it++) {
            int idx = it * 256 + tid, r = idx >> 4, ch = idx & 15;
            int pch = (ch & 8) | ((ch ^ r) & 7);
            cp16(smem_u32(sV + SV_ELEMS + r * 128 + pch * 8), src + (size_t)r * QKVN + 64 + ch * 8);
        }
        cp_commit();
    }
    cp_wait1();          // Q + tile 0 complete; tile 1 may be in flight
    __syncthreads();

    // Q fragment for this warp's 16 rows
    uint32_t aQ[2][4];
    {
        uint32_t sQb = smem_u32(sQ);
        int r = warp * 16 + ((mat & 1) << 3) + rl;
        ldm_x4(aQ[0], sQb + (uint32_t)(r * (QSTR * 2) + (mat >> 1) * 16));
        ldm_x4(aQ[1], sQb + (uint32_t)(r * (QSTR * 2) + 32 + (mat >> 1) * 16));
    }

    uint32_t O[16][2];   // f16x2 accumulators = 32 regs
#pragma unroll
    for (int t = 0; t < 16; t++) { O[t][0] = 0u; O[t][1] = 0u; }
    float l0 = 0.f, l1 = 0.f;
    const uint32_t sKb = smem_u32(sK), sVb = smem_u32(sV);

    int buf = 0;   // buffer of tile kb
    int pt  = 2;   // buffer for tile kb+2
    for (int kb = 0; kb < NKB; kb++) {
        // prefetch tile kb+2 into buffer pt (freed at end of previous iteration)
        if (kb + 2 < NKB) {
            const __half* src = gRow + (size_t)((kb + 2) * KB) * QKVN;
            __half* dK = sK + pt * SK_ELEMS;
            __half* dV = sV + pt * SV_ELEMS;
            {
                int r = tid >> 2, ch = tid & 3;
                cp16(smem_u32(dK + r * QSTR + ch * 8), src + (size_t)r * QKVN + 32 + ch * 8);
            }
#pragma unroll
            for (int it = 0; it < 4; it++) {
                int idx = it * 256 + tid, r = idx >> 4, ch = idx & 15;
                int pch = (ch & 8) | ((ch ^ r) & 7);
                cp16(smem_u32(dV + r * 128 + pch * 8), src + (size_t)r * QKVN + 64 + ch * 8);
            }
            cp_commit();
        }

        const uint32_t kBase = sKb + buf * (SK_ELEMS * 2);
        const uint32_t vBase = sVb + buf * (SV_ELEMS * 2);
        uint32_t rs0 = 0u, rs1 = 0u;   // f16x2 per-kb rowsums
#pragma unroll
        for (int g = 0; g < 4; g++) {
            // S = Q K^T for 16 rows x 16 keys (f16 accum)
            uint32_t S[2][2] = {{0u, 0u}, {0u, 0u}};
#pragma unroll
            for (int ks = 0; ks < 2; ks++) {
                uint32_t b4[4];
                int r = g * 16 + ((mat >> 1) << 3) + rl;
                int ch = ks * 2 + (mat & 1);
                ldm_x4(b4, kBase + (uint32_t)(r * (QSTR * 2) + ch * 16));
                mma_f16(S[0], aQ[ks], b4);
                mma_f16(S[1], aQ[ks], b4 + 2);
            }
            // P = 2^S in place; P == A-fragment layout for PV
            uint32_t aP[4];
            aP[0] = ex2_f16x2(S[0][0]);
            aP[1] = ex2_f16x2(S[0][1]);
            aP[2] = ex2_f16x2(S[1][0]);
            aP[3] = ex2_f16x2(S[1][1]);
            rs0 = hadd2(rs0, hadd2(aP[0], aP[2]));
            rs1 = hadd2(rs1, hadd2(aP[1], aP[3]));
            // O += P V
#pragma unroll
            for (int nt = 0; nt < 8; nt++) {
                uint32_t b4[4];
                int r = g * 16 + ((mat & 1) << 3) + rl;
                int ch = nt * 2 + (mat >> 1);
                int pch = (ch & 8) | ((ch ^ r) & 7);
                ldm_x4t(b4, vBase + (uint32_t)(r * 256 + pch * 16));
                mma_f16(O[2 * nt], aP, b4);
                mma_f16(O[2 * nt + 1], aP, b4 + 2);
            }
        }
        l0 += hsum(rs0);
        l1 += hsum(rs1);

        if (kb < NKB - 1) {
            // need copy(kb+1) complete; allow copy(kb+2) outstanding if committed
            if (kb <= NKB - 3) cp_wait1(); else cp_wait0();
            __syncthreads();   // all warps done reading buf -> safe as next prefetch target
        }
        buf = (buf == 2) ? 0 : buf + 1;
        pt  = (pt == 2) ? 0 : pt + 1;
    }

    // row sums live across the lane quad
    l0 += __shfl_xor_sync(0xffffffffu, l0, 1);
    l0 += __shfl_xor_sync(0xffffffffu, l0, 2);
    l1 += __shfl_xor_sync(0xffffffffu, l1, 1);
    l1 += __shfl_xor_sync(0xffffffffu, l1, 2);
    float inv0 = 1.f / l0, inv1 = 1.f / l1;

    const int row = q0 + warp * 16 + gid;
    __half* gO = g_OW + (size_t)win * NT * Cn;
#pragma unroll
    for (int t = 0; t < 16; t++) {
        int col = t * 8 + tid4 * 2;
        float a, b;
        unpack_f16(O[t][0], a, b);
        *(uint32_t*)(gO + (size_t)row * Cn + col) = pack_f16(a * inv0, b * inv0);
        unpack_f16(O[t][1], a, b);
        *(uint32_t*)(gO + (size_t)(row + 8) * Cn + col) = pack_f16(a * inv1, b * inv1);
    }
}

// ---------------- kernel 4: chess reverse + gamma*out + x ----------------
__global__ __launch_bounds__(256) void k_scatter(const float* __restrict__ x,
                                                 const float* __restrict__ gamma,
                                                 float* __restrict__ out) {
    __shared__ __align__(16) __half s[256 * 66];
    const int h = blockIdx.x, b = blockIdx.y, c0 = blockIdx.z * 64;
    const int tid = threadIdx.x, warp = tid >> 5, lane = tid & 31;
    const int i = h >> 3, py = h & 7;
#pragma unroll
    for (int it = 0; it < 32; it++) {
        int pair = it * 8 + warp;
        int px = pair >> 5, j = pair & 31;
        int win = b * 64 + py * 8 + px;
        int tok = i * 32 + j;
        uint32_t v = *(const uint32_t*)(g_OW + ((size_t)(win * NT + tok) * Cn + c0 + 2 * lane));
        *(uint32_t*)(s + (j * 8 + px) * 66 + 2 * lane) = v;
    }
    __syncthreads();
    const float gm = gamma[0];
    const float* xr = x + ((size_t)(b * Cn + c0) * Hn + h) * Wn;
    float* orow = out + ((size_t)(b * Cn + c0) * Hn + h) * Wn;
#pragma unroll 8
    for (int c = 0; c < 64; c++) {
        float o = __half2float(s[tid * 66 + c]);
        orow[(size_t)c * Hn * Wn + tid] = gm * o + xr[(size_t)c * Hn * Wn + tid];
    }
}

// ---------------- launch ----------------
extern "C" void kernel_launch(void* const* d_in, const int* in_sizes, int n_in,
                              void* d_out, int out_size) {
    const float* x  = (const float*)d_in[0];
    const float* Wq = (const float*)d_in[1];
    const float* bq = (const float*)d_in[2];
    const float* Wk = (const float*)d_in[3];
    const float* bk = (const float*)d_in[4];
    const float* Wv = (const float*)d_in[5];
    const float* bv = (const float*)d_in[6];
    const float* gamma = (const float*)d_in[7];

    cudaFuncSetAttribute(k_proj, cudaFuncAttributeMaxDynamicSharedMemorySize, PROJ_SMEM);
    cudaFuncSetAttribute(k_attn, cudaFuncAttributeMaxDynamicSharedMemorySize, ATTN_SMEM_BYTES);

    k_pack<<<(Cn * QKVN + 255) / 256, 256>>>(Wq, Wk, Wv);
    k_gather<<<dim3(Hn, Bn, 2), 256>>>(x);
    k_proj<<<dim3(NT / PROJ_MT, NWIN), 128, PROJ_SMEM>>>(bq, bk, bv);
    k_attn<<<dim3(8, NWIN), 256, ATTN_SMEM_BYTES>>>();
    k_scatter<<<dim3(Hn, Bn, 2), 256>>>(x, gamma, (float*)d_out);
}